// round 2
// baseline (speedup 1.0000x reference)
#include <cuda_runtime.h>
#include <mma.h>
#include <math.h>

using namespace nvcuda;

// Problem constants
#define Bq   256
#define Tq   256
#define Cq   384
#define Hq   64
#define BT   (Bq * Tq)

// Scratch for q, k, v projections ([B, T, H] fp32 each)
__device__ float g_q[(size_t)BT * Hq];
__device__ float g_k[(size_t)BT * Hq];
__device__ float g_v[(size_t)BT * Hq];

// ----------------------------------------------------------------------------
// Kernel 1: fused QKV projection via tf32 tensor cores (wmma m16n16k8).
// One block computes a 128-row x-tile against all three weights (N = 3*64 = 192),
// reading x only once. 256 threads = 8 warps in a 4(M) x 2(N) grid;
// each warp owns a 32x96 output tile (2x6 fragments).
// ----------------------------------------------------------------------------
#define PM 128
#define PN 192
#define PK 32
#define A_LD (PK + 4)    // 36 floats -> 144B row stride (16B aligned)
#define B_LD (PN + 4)    // 196 floats -> 784B row stride (16B aligned)

__global__ __launch_bounds__(256) void proj_wmma(
    const float* __restrict__ x,
    const float* __restrict__ Wq,
    const float* __restrict__ Wk,
    const float* __restrict__ Wv)
{
    __shared__ __align__(16) float As[PM][A_LD];
    __shared__ __align__(16) float Bs[PK][B_LD];

    const int tid  = threadIdx.x;
    const int warp = tid >> 5;
    const int wm   = warp >> 1;   // 0..3
    const int wn   = warp & 1;    // 0..1
    const int m0   = blockIdx.x * PM;

    const float* Ws[3] = {Wq, Wk, Wv};

    wmma::fragment<wmma::accumulator, 16, 16, 8, float> acc[2][6];
    #pragma unroll
    for (int i = 0; i < 2; i++)
        #pragma unroll
        for (int j = 0; j < 6; j++)
            wmma::fill_fragment(acc[i][j], 0.0f);

    for (int kc = 0; kc < Cq / PK; kc++) {
        const int k0 = kc * PK;

        // Load A tile: 128 x 32 floats = 1024 float4, 4 per thread
        #pragma unroll
        for (int i = 0; i < 4; i++) {
            int idx = tid + i * 256;          // 0..1023
            int row = idx >> 3;               // 0..127
            int kq  = idx & 7;                // 0..7
            *(float4*)&As[row][kq * 4] =
                *(const float4*)&x[(size_t)(m0 + row) * Cq + k0 + kq * 4];
        }
        // Load B tile: 32 x 192 floats = 1536 float4, 6 per thread
        #pragma unroll
        for (int i = 0; i < 6; i++) {
            int idx = tid + i * 256;          // 0..1535
            int k   = idx / 48;               // 0..31
            int c4  = idx % 48;               // float4 index in row
            int wch = c4 >> 4;                // which weight
            int nc  = (c4 & 15) * 4;          // col within weight
            *(float4*)&Bs[k][c4 * 4] =
                *(const float4*)&Ws[wch][(size_t)(k0 + k) * Hq + nc];
        }
        __syncthreads();

        #pragma unroll
        for (int ks = 0; ks < 4; ks++) {
            const int k = ks * 8;
            wmma::fragment<wmma::matrix_a, 16, 16, 8, wmma::precision::tf32, wmma::row_major> a[2];
            wmma::fragment<wmma::matrix_b, 16, 16, 8, wmma::precision::tf32, wmma::row_major> b[6];
            #pragma unroll
            for (int i = 0; i < 2; i++) {
                wmma::load_matrix_sync(a[i], &As[wm * 32 + i * 16][k], A_LD);
                #pragma unroll
                for (int t = 0; t < a[i].num_elements; t++)
                    a[i].x[t] = wmma::__float_to_tf32(a[i].x[t]);
            }
            #pragma unroll
            for (int j = 0; j < 6; j++) {
                wmma::load_matrix_sync(b[j], &Bs[k][wn * 96 + j * 16], B_LD);
                #pragma unroll
                for (int t = 0; t < b[j].num_elements; t++)
                    b[j].x[t] = wmma::__float_to_tf32(b[j].x[t]);
            }
            #pragma unroll
            for (int i = 0; i < 2; i++)
                #pragma unroll
                for (int j = 0; j < 6; j++)
                    wmma::mma_sync(acc[i][j], a[i], b[j], acc[i][j]);
        }
        __syncthreads();
    }

    // Epilogue: scatter fragments to g_q / g_k / g_v
    float* outs[3] = {g_q, g_k, g_v};
    #pragma unroll
    for (int i = 0; i < 2; i++) {
        #pragma unroll
        for (int j = 0; j < 6; j++) {
            int gcol = wn * 96 + j * 16;
            int wch  = gcol / 64;
            int ncol = gcol % 64;
            int row  = m0 + wm * 32 + i * 16;
            wmma::store_matrix_sync(&outs[wch][(size_t)row * Hq + ncol],
                                    acc[i][j], Hq, wmma::mem_row_major);
        }
    }
}

// ----------------------------------------------------------------------------
// Kernel 2: causal flash attention, 64-query chunks.
// Block (qc, b): queries [qc*64, qc*64+64). 256 threads: 4 threads per query
// row, each owning 16 of the 64 head dims. Scores reduced across the 4
// partner lanes via shfl_xor. Online softmax per row.
// ----------------------------------------------------------------------------
#define QC 64

__global__ __launch_bounds__(256) void attn_kernel(float* __restrict__ outp)
{
    __shared__ __align__(16) float Kt[QC][Hq];
    __shared__ __align__(16) float Vt[QC][Hq];

    const int qc  = blockIdx.x;
    const int b   = blockIdx.y;
    const int tid = threadIdx.x;
    const int r   = tid >> 2;          // local query row 0..63
    const int p   = tid & 3;           // head-dim quarter
    const int qg  = qc * QC + r;       // global query row

    const unsigned lane  = tid & 31;
    const unsigned gmask = 0xFu << (lane & 28);   // 4-lane partner group

    // Per-thread q slice (16 dims) in registers
    float4 q[4];
    {
        const float4* qr = (const float4*)(g_q + ((size_t)b * Tq + qg) * Hq + p * 16);
        #pragma unroll
        for (int i = 0; i < 4; i++) q[i] = qr[i];
    }
    float4 o[4];
    #pragma unroll
    for (int i = 0; i < 4; i++) o[i] = make_float4(0.f, 0.f, 0.f, 0.f);

    const float scale = 1.0f / sqrtf((float)Cq);
    float m = -INFINITY;
    float l = 0.0f;

    for (int jt = 0; jt <= qc; jt++) {
        __syncthreads();
        const float4* kb = (const float4*)(g_k + ((size_t)b * Tq + jt * QC) * Hq);
        const float4* vb = (const float4*)(g_v + ((size_t)b * Tq + jt * QC) * Hq);
        #pragma unroll
        for (int i = 0; i < 4; i++) {
            int idx = tid + i * 256;          // 0..1023 float4 slots
            ((float4*)Kt)[idx] = kb[idx];
            ((float4*)Vt)[idx] = vb[idx];
        }
        __syncthreads();

        const int jmax = (jt == qc) ? (r + 1) : QC;
        for (int j = 0; j < jmax; j++) {
            const float4* kr = (const float4*)&Kt[j][p * 16];
            float s = 0.f;
            #pragma unroll
            for (int i = 0; i < 4; i++) {
                float4 k4 = kr[i];
                s += q[i].x * k4.x + q[i].y * k4.y + q[i].z * k4.z + q[i].w * k4.w;
            }
            s += __shfl_xor_sync(gmask, s, 1);
            s += __shfl_xor_sync(gmask, s, 2);
            s *= scale;

            float pj;
            if (s > m) {
                float corr = __expf(m - s);   // first iter: exp(-inf)=0
                m = s;
                l *= corr;
                #pragma unroll
                for (int i = 0; i < 4; i++) {
                    o[i].x *= corr; o[i].y *= corr;
                    o[i].z *= corr; o[i].w *= corr;
                }
                pj = 1.0f;
            } else {
                pj = __expf(s - m);
            }
            l += pj;

            const float4* vr = (const float4*)&Vt[j][p * 16];
            #pragma unroll
            for (int i = 0; i < 4; i++) {
                float4 v4 = vr[i];
                o[i].x += pj * v4.x; o[i].y += pj * v4.y;
                o[i].z += pj * v4.z; o[i].w += pj * v4.w;
            }
        }
    }

    const float inv = 1.0f / l;
    float4* orow = (float4*)(outp + ((size_t)b * Tq + qg) * Hq + p * 16);
    #pragma unroll
    for (int i = 0; i < 4; i++) {
        float4 v = o[i];
        v.x *= inv; v.y *= inv; v.z *= inv; v.w *= inv;
        orow[i] = v;
    }
}

// ----------------------------------------------------------------------------
extern "C" void kernel_launch(void* const* d_in, const int* in_sizes, int n_in,
                              void* d_out, int out_size)
{
    const float* x  = (const float*)d_in[0];
    const float* Wq = (const float*)d_in[1];
    const float* Wk = (const float*)d_in[2];
    const float* Wv = (const float*)d_in[3];
    float* out = (float*)d_out;

    (void)in_sizes; (void)n_in; (void)out_size;

    proj_wmma<<<BT / PM, 256>>>(x, Wq, Wk, Wv);

    dim3 ga(Tq / QC, Bq);
    attn_kernel<<<ga, 256>>>(out);
}

// round 3
// speedup vs baseline: 1.0849x; 1.0849x over previous
#include <cuda_runtime.h>
#include <math.h>

// Problem constants
#define Bq   256
#define Tq   256
#define Cq   384
#define Hq   64
#define BT   (Bq * Tq)

// Scratch for q, k, v projections ([B, T, H] fp32 each)
__device__ float g_q[(size_t)BT * Hq];
__device__ float g_k[(size_t)BT * Hq];
__device__ float g_v[(size_t)BT * Hq];

// ---------------------------------------------------------------------------
// Packed f32x2 helpers (FFMA2 — only reachable via PTX, 2x FFMA issue rate)
// ---------------------------------------------------------------------------
typedef unsigned long long ull;

__device__ __forceinline__ ull ffma2(ull a, ull b, ull c) {
    ull d;
    asm("fma.rn.f32x2 %0, %1, %2, %3;" : "=l"(d) : "l"(a), "l"(b), "l"(c));
    return d;
}
__device__ __forceinline__ ull dup2(float x) {
    ull d;
    asm("mov.b64 %0, {%1, %1};" : "=l"(d) : "f"(x));
    return d;
}
__device__ __forceinline__ float2 unpack2(ull v) {
    float2 r;
    asm("mov.b64 {%0, %1}, %2;" : "=f"(r.x), "=f"(r.y) : "l"(v));
    return r;
}

// ---------------------------------------------------------------------------
// Kernel 1: QKV projection SGEMM with FFMA2.
// [BT x C] @ [C x 64] -> [BT x 64].  Tile: 128(M) x 64(N), BK=32, 256 threads.
// Micro-tile 4 rows x 8 cols (4 packed col-pairs). grid.y selects weight.
// x (100MB) fits in L2 (126MB) so the 3x re-read is cheap.
// ---------------------------------------------------------------------------
#define PM 128
#define PBK 32

__global__ __launch_bounds__(256) void proj_kernel(
    const float* __restrict__ x,
    const float* __restrict__ Wq,
    const float* __restrict__ Wk,
    const float* __restrict__ Wv)
{
    const int which = blockIdx.y;
    const float* __restrict__ W = (which == 0) ? Wq : (which == 1) ? Wk : Wv;
    float* __restrict__ out     = (which == 0) ? g_q : (which == 1) ? g_k : g_v;

    __shared__ float As[PM][PBK + 1];          // [m][k], pad -> conflict-free
    __shared__ __align__(16) float Bs[PBK][Hq]; // [k][n]

    const int tid = threadIdx.x;
    const int tx  = tid & 7;    // col group: 8 cols
    const int ty  = tid >> 3;   // row group: 4 rows
    const int m0  = blockIdx.x * PM;

    ull acc[4][4];
    #pragma unroll
    for (int r = 0; r < 4; r++)
        #pragma unroll
        for (int j = 0; j < 4; j++) acc[r][j] = 0ull;

    for (int k0 = 0; k0 < Cq; k0 += PBK) {
        // A tile: 128 x 32 floats = 1024 float4, 4 per thread (scatter scalar)
        #pragma unroll
        for (int i = 0; i < 4; i++) {
            int idx = tid + i * 256;
            int row = idx >> 3;
            int kq  = idx & 7;
            float4 v = *(const float4*)&x[(size_t)(m0 + row) * Cq + k0 + kq * 4];
            As[row][kq * 4 + 0] = v.x;
            As[row][kq * 4 + 1] = v.y;
            As[row][kq * 4 + 2] = v.z;
            As[row][kq * 4 + 3] = v.w;
        }
        // B tile: 32 x 64 floats = 512 float4, 2 per thread
        #pragma unroll
        for (int i = 0; i < 2; i++) {
            int idx = tid + i * 256;
            int k   = idx >> 4;
            int nq  = idx & 15;
            *(float4*)&Bs[k][nq * 4] =
                *(const float4*)&W[(size_t)(k0 + k) * Hq + nq * 4];
        }
        __syncthreads();

        #pragma unroll
        for (int kk = 0; kk < PBK; kk++) {
            ull ad[4];
            #pragma unroll
            for (int r = 0; r < 4; r++) ad[r] = dup2(As[ty * 4 + r][kk]);
            // 8 cols = 4 packed pairs, read as two 16B chunks
            longlong2 b01 = *(const longlong2*)&Bs[kk][tx * 8];
            longlong2 b23 = *(const longlong2*)&Bs[kk][tx * 8 + 4];
            ull bp[4] = {(ull)b01.x, (ull)b01.y, (ull)b23.x, (ull)b23.y};
            #pragma unroll
            for (int r = 0; r < 4; r++)
                #pragma unroll
                for (int j = 0; j < 4; j++)
                    acc[r][j] = ffma2(ad[r], bp[j], acc[r][j]);
        }
        __syncthreads();
    }

    #pragma unroll
    for (int r = 0; r < 4; r++) {
        float2 p0 = unpack2(acc[r][0]);
        float2 p1 = unpack2(acc[r][1]);
        float2 p2 = unpack2(acc[r][2]);
        float2 p3 = unpack2(acc[r][3]);
        float* orow = &out[(size_t)(m0 + ty * 4 + r) * Hq + tx * 8];
        *(float4*)orow       = make_float4(p0.x, p0.y, p1.x, p1.y);
        *(float4*)(orow + 4) = make_float4(p2.x, p2.y, p3.x, p3.y);
    }
}

// ---------------------------------------------------------------------------
// Kernel 2: causal attention, thread-per-query-row, FFMA2 inner loops.
// Block (h, b): query rows [h*128, h*128+128), 128 threads (one per row).
// K/V staged in 128-row chunks (64KB dynamic smem) -> ~3 CTAs/SM.
// All active threads read the same K/V row -> broadcast LDS (conflict-free).
// ---------------------------------------------------------------------------
#define QR 128   // query rows per block / rows per K,V chunk

__global__ __launch_bounds__(128) void attn_kernel(float* __restrict__ outp)
{
    extern __shared__ __align__(16) float smem[];
    float* Kc = smem;             // [QR][Hq]
    float* Vc = smem + QR * Hq;   // [QR][Hq]

    const int h   = blockIdx.x;        // 0 or 1
    const int b   = blockIdx.y;
    const int tid = threadIdx.x;
    const int row = h * QR + tid;      // global query row

    // q row (64 floats) as 32 packed pairs
    ull qp[32];
    {
        const longlong2* qr = (const longlong2*)(g_q + ((size_t)b * Tq + row) * Hq);
        #pragma unroll
        for (int i = 0; i < 16; i++) {
            longlong2 v = qr[i];
            qp[2 * i]     = (ull)v.x;
            qp[2 * i + 1] = (ull)v.y;
        }
    }
    ull o2[32];
    #pragma unroll
    for (int i = 0; i < 32; i++) o2[i] = 0ull;

    const float scale = 1.0f / sqrtf((float)Cq);
    float m = -INFINITY;
    float l = 0.0f;

    for (int jt = 0; jt <= h; jt++) {
        __syncthreads();
        // Stage K/V chunk: 128 rows x 64 floats = 2048 float4 each
        const float4* kb = (const float4*)(g_k + ((size_t)b * Tq + jt * QR) * Hq);
        const float4* vb = (const float4*)(g_v + ((size_t)b * Tq + jt * QR) * Hq);
        #pragma unroll
        for (int i = 0; i < 16; i++) {
            int idx = tid + i * 128;
            ((float4*)Kc)[idx] = kb[idx];
            ((float4*)Vc)[idx] = vb[idx];
        }
        __syncthreads();

        const int jmax = (jt == h) ? (tid + 1) : QR;
        for (int j = 0; j < jmax; j++) {
            const longlong2* kr = (const longlong2*)(Kc + j * Hq);
            ull s2[4] = {0ull, 0ull, 0ull, 0ull};
            #pragma unroll
            for (int i = 0; i < 16; i++) {
                longlong2 kv = kr[i];
                s2[(2 * i) & 3]     = ffma2(qp[2 * i],     (ull)kv.x, s2[(2 * i) & 3]);
                s2[(2 * i + 1) & 3] = ffma2(qp[2 * i + 1], (ull)kv.y, s2[(2 * i + 1) & 3]);
            }
            float2 u0 = unpack2(s2[0]), u1 = unpack2(s2[1]);
            float2 u2 = unpack2(s2[2]), u3 = unpack2(s2[3]);
            float s = ((u0.x + u0.y) + (u1.x + u1.y)) +
                      ((u2.x + u2.y) + (u3.x + u3.y));
            s *= scale;

            float pj;
            if (s > m) {
                float corr = __expf(m - s);    // first iter: exp(-inf)=0
                m = s;
                l *= corr;
                ull cd = dup2(corr);
                ull z  = 0ull;
                #pragma unroll
                for (int i = 0; i < 32; i++) o2[i] = ffma2(cd, o2[i], z);
                pj = 1.0f;
            } else {
                pj = __expf(s - m);
            }
            l += pj;

            ull pd = dup2(pj);
            const longlong2* vr = (const longlong2*)(Vc + j * Hq);
            #pragma unroll
            for (int i = 0; i < 16; i++) {
                longlong2 vv = vr[i];
                o2[2 * i]     = ffma2(pd, (ull)vv.x, o2[2 * i]);
                o2[2 * i + 1] = ffma2(pd, (ull)vv.y, o2[2 * i + 1]);
            }
        }
    }

    const float inv = 1.0f / l;
    float* orow = outp + ((size_t)b * Tq + row) * Hq;
    #pragma unroll
    for (int i = 0; i < 16; i++) {
        float2 a = unpack2(o2[2 * i]);
        float2 c = unpack2(o2[2 * i + 1]);
        *(float4*)(orow + i * 4) =
            make_float4(a.x * inv, a.y * inv, c.x * inv, c.y * inv);
    }
}

// ---------------------------------------------------------------------------
extern "C" void kernel_launch(void* const* d_in, const int* in_sizes, int n_in,
                              void* d_out, int out_size)
{
    const float* x  = (const float*)d_in[0];
    const float* Wq = (const float*)d_in[1];
    const float* Wk = (const float*)d_in[2];
    const float* Wv = (const float*)d_in[3];
    float* out = (float*)d_out;

    (void)in_sizes; (void)n_in; (void)out_size;

    dim3 gp(BT / PM, 3);
    proj_kernel<<<gp, 256>>>(x, Wq, Wk, Wv);

    const int smem_bytes = 2 * QR * Hq * (int)sizeof(float);  // 64 KB
    cudaFuncSetAttribute(attn_kernel,
                         cudaFuncAttributeMaxDynamicSharedMemorySize,
                         smem_bytes);
    dim3 ga(Tq / QR, Bq);
    attn_kernel<<<ga, 128, smem_bytes>>>(out);
}